// round 1
// baseline (speedup 1.0000x reference)
#include <cuda_runtime.h>
#include <math.h>

// ============================================================================
// CrossAttention: out = softmax((xWq+bq)(yWk+bk)^T / 8) (yWv+bv) Wo + bo
// B=4, SQ=SKV=2048, D_EMBED=1024, D_CROSS=768, H=16, DH=64
// All-fp32 round-0 implementation: tiled SGEMM + fp32 flash attention.
// ============================================================================

#define M_ROWS 8192        // B*SQ = B*SKV
#define N_ATT  1024        // D_ATT
#define HEADS  16
#define DHEAD  64
#define SEQ    2048

// Scratch: [B,H,S,DH] for q,k,v ; [B*S, D_ATT] for attn output
__device__ float g_q[8388608];
__device__ float g_k[8388608];
__device__ float g_v[8388608];
__device__ float g_attn[8388608];

// ----------------------------------------------------------------------------
// SGEMM: C = A(MxK) * B(KxN) + bias(N).  128x128 tile, BK=8, 256 threads,
// 8x8 per-thread micro-tile, double-buffered smem.
// mode 0: C row-major [M,N]
// mode 1: C written as [B,H,S,DH] scratch (head split) with m=b*2048+s, n=h*64+d
// ----------------------------------------------------------------------------
__global__ __launch_bounds__(256) void gemm_bias_kernel(
    const float* __restrict__ A, const float* __restrict__ B,
    const float* __restrict__ bias, float* __restrict__ C,
    int M, int N, int K, int mode)
{
    __shared__ float As[2][8][128];   // transposed: As[k][row]
    __shared__ float Bs[2][8][128];   // Bs[k][col]

    const int tid = threadIdx.x;
    const int ty  = tid >> 4;         // 0..15
    const int tx  = tid & 15;         // 0..15
    const int rowBase = blockIdx.y * 128;
    const int colBase = blockIdx.x * 128;

    const int ar = tid >> 1;          // 0..127
    const int ac = (tid & 1) << 2;    // 0 or 4
    const int br = tid >> 5;          // 0..7
    const int bc = (tid & 31) << 2;   // 0..124

    const float* Ag = A + (size_t)(rowBase + ar) * K + ac;
    const float* Bg = B + (size_t)br * N + colBase + bc;

    float acc[8][8];
    #pragma unroll
    for (int i = 0; i < 8; i++)
        #pragma unroll
        for (int j = 0; j < 8; j++) acc[i][j] = 0.f;

    // prologue: tile 0
    {
        float4 a4 = *(const float4*)Ag;
        float4 b4 = *(const float4*)Bg;
        As[0][ac+0][ar] = a4.x; As[0][ac+1][ar] = a4.y;
        As[0][ac+2][ar] = a4.z; As[0][ac+3][ar] = a4.w;
        *(float4*)&Bs[0][br][bc] = b4;
    }
    __syncthreads();

    const int nT = K >> 3;
    for (int t = 0; t < nT; t++) {
        const int cur = t & 1;
        const int nxt = cur ^ 1;
        float4 na, nb;
        const bool more = (t + 1 < nT);
        if (more) {
            na = *(const float4*)(Ag + (t + 1) * 8);
            nb = *(const float4*)(Bg + (size_t)(t + 1) * 8 * N);
        }
        #pragma unroll
        for (int k = 0; k < 8; k++) {
            float4 ra0 = *(const float4*)&As[cur][k][ty * 8];
            float4 ra1 = *(const float4*)&As[cur][k][ty * 8 + 4];
            float4 rb0 = *(const float4*)&Bs[cur][k][tx * 8];
            float4 rb1 = *(const float4*)&Bs[cur][k][tx * 8 + 4];
            float ra[8] = {ra0.x, ra0.y, ra0.z, ra0.w, ra1.x, ra1.y, ra1.z, ra1.w};
            float rb[8] = {rb0.x, rb0.y, rb0.z, rb0.w, rb1.x, rb1.y, rb1.z, rb1.w};
            #pragma unroll
            for (int i = 0; i < 8; i++)
                #pragma unroll
                for (int j = 0; j < 8; j++)
                    acc[i][j] += ra[i] * rb[j];
        }
        if (more) {
            As[nxt][ac+0][ar] = na.x; As[nxt][ac+1][ar] = na.y;
            As[nxt][ac+2][ar] = na.z; As[nxt][ac+3][ar] = na.w;
            *(float4*)&Bs[nxt][br][bc] = nb;
            __syncthreads();
        }
    }

    #pragma unroll
    for (int i = 0; i < 8; i++) {
        const int m = rowBase + ty * 8 + i;
        #pragma unroll
        for (int jj = 0; jj < 2; jj++) {
            const int n = colBase + tx * 8 + jj * 4;
            float4 v;
            v.x = acc[i][jj*4+0] + bias[n+0];
            v.y = acc[i][jj*4+1] + bias[n+1];
            v.z = acc[i][jj*4+2] + bias[n+2];
            v.w = acc[i][jj*4+3] + bias[n+3];
            if (mode == 0) {
                *(float4*)&C[(size_t)m * N + n] = v;
            } else {
                const int b = m >> 11, s = m & 2047;
                const int h = n >> 6, d = n & 63;
                const size_t off = (((size_t)(b * HEADS + h)) * SEQ + s) * DHEAD + d;
                *(float4*)&C[off] = v;
            }
        }
    }
}

// ----------------------------------------------------------------------------
// fp32 flash attention: per (b,h,qblock of 64). KV tiles of 64.
// smem: Qs[64][68] (pre-scaled), Kt[64 d][68 kv], Vs[64 kv][68 d], Ps[64][68]
// threads: 256 = 16x16, each thread owns a 4x4 tile of S / O.
// ----------------------------------------------------------------------------
#define SST 68
#define ATTN_SMEM (4 * 64 * SST * 4)

__global__ __launch_bounds__(256) void attn_kernel(
    const float* __restrict__ Qg_, const float* __restrict__ Kg_,
    const float* __restrict__ Vg_, float* __restrict__ Out)
{
    extern __shared__ float sm[];
    float* Qs = sm;
    float* Kt = sm + 64 * SST;
    float* Vs = sm + 2 * 64 * SST;
    float* Ps = sm + 3 * 64 * SST;

    const int tid = threadIdx.x;
    const int ty  = tid >> 4;
    const int tx  = tid & 15;
    const int qb  = blockIdx.x;   // 0..31
    const int h   = blockIdx.y;   // 0..15
    const int b   = blockIdx.z;   // 0..3

    const size_t headOff = ((size_t)(b * HEADS + h)) * SEQ * DHEAD;
    const float* Qg = Qg_ + headOff + (size_t)qb * 64 * DHEAD;
    const float* Kg = Kg_ + headOff;
    const float* Vg = Vg_ + headOff;

    // Load Q tile, pre-scaled by 1/sqrt(64)
    #pragma unroll
    for (int i = 0; i < 4; i++) {
        const int idx = tid + i * 256;
        const int r = idx >> 4;
        const int c = (idx & 15) << 2;
        float4 q4 = *(const float4*)(Qg + r * DHEAD + c);
        q4.x *= 0.125f; q4.y *= 0.125f; q4.z *= 0.125f; q4.w *= 0.125f;
        *(float4*)&Qs[r * SST + c] = q4;
    }

    float m_i[4], l_i[4], o[4][4];
    #pragma unroll
    for (int i = 0; i < 4; i++) {
        m_i[i] = -1e30f; l_i[i] = 0.f;
        #pragma unroll
        for (int j = 0; j < 4; j++) o[i][j] = 0.f;
    }

    for (int kv0 = 0; kv0 < SEQ; kv0 += 64) {
        __syncthreads();  // prev-iter PV done reading Vs/Ps; Qs visible (1st iter)
        #pragma unroll
        for (int i = 0; i < 4; i++) {
            const int idx = tid + i * 256;
            const int r = idx >> 4;
            const int c = (idx & 15) << 2;
            float4 k4 = *(const float4*)(Kg + (size_t)(kv0 + r) * DHEAD + c);
            Kt[(c + 0) * SST + r] = k4.x;
            Kt[(c + 1) * SST + r] = k4.y;
            Kt[(c + 2) * SST + r] = k4.z;
            Kt[(c + 3) * SST + r] = k4.w;
            float4 v4 = *(const float4*)(Vg + (size_t)(kv0 + r) * DHEAD + c);
            *(float4*)&Vs[r * SST + c] = v4;
        }
        __syncthreads();

        // S = (Q*scale) K^T : 4x4 per thread
        float s[4][4];
        #pragma unroll
        for (int i = 0; i < 4; i++)
            #pragma unroll
            for (int j = 0; j < 4; j++) s[i][j] = 0.f;

        #pragma unroll 16
        for (int d = 0; d < 64; d++) {
            const float4 kb = *(const float4*)&Kt[d * SST + tx * 4];
            const float q0 = Qs[(ty * 4 + 0) * SST + d];
            const float q1 = Qs[(ty * 4 + 1) * SST + d];
            const float q2 = Qs[(ty * 4 + 2) * SST + d];
            const float q3 = Qs[(ty * 4 + 3) * SST + d];
            s[0][0] += q0 * kb.x; s[0][1] += q0 * kb.y; s[0][2] += q0 * kb.z; s[0][3] += q0 * kb.w;
            s[1][0] += q1 * kb.x; s[1][1] += q1 * kb.y; s[1][2] += q1 * kb.z; s[1][3] += q1 * kb.w;
            s[2][0] += q2 * kb.x; s[2][1] += q2 * kb.y; s[2][2] += q2 * kb.z; s[2][3] += q2 * kb.w;
            s[3][0] += q3 * kb.x; s[3][1] += q3 * kb.y; s[3][2] += q3 * kb.z; s[3][3] += q3 * kb.w;
        }

        // online softmax; row reductions across the 16 tx lanes (half-warp)
        #pragma unroll
        for (int i = 0; i < 4; i++) {
            float mx = fmaxf(fmaxf(s[i][0], s[i][1]), fmaxf(s[i][2], s[i][3]));
            mx = fmaxf(mx, __shfl_xor_sync(0xffffffffu, mx, 1));
            mx = fmaxf(mx, __shfl_xor_sync(0xffffffffu, mx, 2));
            mx = fmaxf(mx, __shfl_xor_sync(0xffffffffu, mx, 4));
            mx = fmaxf(mx, __shfl_xor_sync(0xffffffffu, mx, 8));
            const float mnew = fmaxf(m_i[i], mx);
            const float corr = __expf(m_i[i] - mnew);
            const float p0 = __expf(s[i][0] - mnew);
            const float p1 = __expf(s[i][1] - mnew);
            const float p2 = __expf(s[i][2] - mnew);
            const float p3 = __expf(s[i][3] - mnew);
            float rs = p0 + p1 + p2 + p3;
            rs += __shfl_xor_sync(0xffffffffu, rs, 1);
            rs += __shfl_xor_sync(0xffffffffu, rs, 2);
            rs += __shfl_xor_sync(0xffffffffu, rs, 4);
            rs += __shfl_xor_sync(0xffffffffu, rs, 8);
            l_i[i] = l_i[i] * corr + rs;
            m_i[i] = mnew;
            o[i][0] *= corr; o[i][1] *= corr; o[i][2] *= corr; o[i][3] *= corr;
            *(float4*)&Ps[(ty * 4 + i) * SST + tx * 4] = make_float4(p0, p1, p2, p3);
        }
        __syncthreads();

        // O += P V
        #pragma unroll 16
        for (int d = 0; d < 64; d++) {
            const float4 vb = *(const float4*)&Vs[d * SST + tx * 4];
            const float p0 = Ps[(ty * 4 + 0) * SST + d];
            const float p1 = Ps[(ty * 4 + 1) * SST + d];
            const float p2 = Ps[(ty * 4 + 2) * SST + d];
            const float p3 = Ps[(ty * 4 + 3) * SST + d];
            o[0][0] += p0 * vb.x; o[0][1] += p0 * vb.y; o[0][2] += p0 * vb.z; o[0][3] += p0 * vb.w;
            o[1][0] += p1 * vb.x; o[1][1] += p1 * vb.y; o[1][2] += p1 * vb.z; o[1][3] += p1 * vb.w;
            o[2][0] += p2 * vb.x; o[2][1] += p2 * vb.y; o[2][2] += p2 * vb.z; o[2][3] += p2 * vb.w;
            o[3][0] += p3 * vb.x; o[3][1] += p3 * vb.y; o[3][2] += p3 * vb.z; o[3][3] += p3 * vb.w;
        }
    }

    // epilogue: normalize and write to [B*S, D_ATT] row-major (head interleave)
    #pragma unroll
    for (int i = 0; i < 4; i++) {
        const float inv = 1.0f / l_i[i];
        const int row = qb * 64 + ty * 4 + i;
        const size_t off = ((size_t)b * SEQ + row) * N_ATT + h * DHEAD + tx * 4;
        *(float4*)&Out[off] = make_float4(o[i][0] * inv, o[i][1] * inv,
                                          o[i][2] * inv, o[i][3] * inv);
    }
}

// ----------------------------------------------------------------------------
// Launch
// ----------------------------------------------------------------------------
extern "C" void kernel_launch(void* const* d_in, const int* in_sizes, int n_in,
                              void* d_out, int out_size)
{
    const float* x  = (const float*)d_in[0];   // [4,2048,1024]
    const float* y  = (const float*)d_in[1];   // [4,2048,768]
    const float* Wq = (const float*)d_in[2];   // [1024,1024]
    const float* bq = (const float*)d_in[3];
    const float* Wk = (const float*)d_in[4];   // [768,1024]
    const float* bk = (const float*)d_in[5];
    const float* Wv = (const float*)d_in[6];   // [768,1024]
    const float* bv = (const float*)d_in[7];
    const float* Wo = (const float*)d_in[8];   // [1024,1024]
    const float* bo = (const float*)d_in[9];
    float* out = (float*)d_out;

    float *gq, *gk, *gv, *ga;
    cudaGetSymbolAddress((void**)&gq, g_q);
    cudaGetSymbolAddress((void**)&gk, g_k);
    cudaGetSymbolAddress((void**)&gv, g_v);
    cudaGetSymbolAddress((void**)&ga, g_attn);

    dim3 blk(256);
    dim3 gGemm(N_ATT / 128, M_ROWS / 128);   // (8, 64)

    // Projections (head-split epilogue)
    gemm_bias_kernel<<<gGemm, blk>>>(x, Wq, bq, gq, M_ROWS, N_ATT, 1024, 1);
    gemm_bias_kernel<<<gGemm, blk>>>(y, Wk, bk, gk, M_ROWS, N_ATT, 768, 1);
    gemm_bias_kernel<<<gGemm, blk>>>(y, Wv, bv, gv, M_ROWS, N_ATT, 768, 1);

    // Flash attention
    cudaFuncSetAttribute(attn_kernel, cudaFuncAttributeMaxDynamicSharedMemorySize,
                         ATTN_SMEM);
    attn_kernel<<<dim3(SEQ / 64, HEADS, 4), blk, ATTN_SMEM>>>(gq, gk, gv, ga);

    // Output projection (plain row-major write to d_out)
    gemm_bias_kernel<<<gGemm, blk>>>(ga, Wo, bo, out, M_ROWS, N_ATT, 1024, 0);
}